// round 10
// baseline (speedup 1.0000x reference)
#include <cuda_runtime.h>
#include <cuda_fp16.h>
#include <cuda_fp8.h>
#include <math.h>

#define B 64
#define C 32
#define D 256
#define F (C * D)          // 8192
#define BC (B * C)         // 2048
#define TEMP 0.1f
#define EPS 1e-8f

#define I_TILE 4
#define J_TILE 8
// dynamic smem layout (bytes)
#define SM_ANCH 0                       // 4 anchors fp8: 4*8192 = 32768
#define SM_J8   32768                   // 8 jb blocks of js fp8: 65536
#define SM_K8   98304                   // 8 jb blocks of is fp8: 65536
#define SM_RNJ  163840                  // 256 floats
#define SM_RNK  164864                  // 256 floats
#define SM_NA   165888                  // 4 floats
#define SM_TOTAL 165920

// ---------------- scratch (no allocations allowed) ----------------
__device__ unsigned char g_is_f8[BC * D];   // fp8 e4m3 (512 KB)
__device__ unsigned char g_js_f8[BC * D];   // fp8 e4m3 (512 KB)
__device__ float g_rn2_is[BC];              // per-row squared norms (fp32)
__device__ float g_rn2_js[BC];
__device__ float g_pd[BC];                  // per-row positive partial dots
__device__ float g_sims[B][2 * B];          // [i][0..B)=sim_j, [B..2B)=sim_k
__device__ float g_lse[B];                  // per-anchor (lse - pos)
__device__ unsigned g_done = 0;             // arrival counter for fused final

__device__ __forceinline__ __half2 f8_to_h2(unsigned short s) {
    __half2_raw hr = __nv_cvt_fp8x2_to_halfraw2((__nv_fp8x2_storage_t)s, __NV_E4M3);
    return *reinterpret_cast<__half2*>(&hr);
}

// ---------------- kernel 1: prep ----------------
// 1024 CTAs x 256 thr: 2 rows per CTA, 4 warps per row, float2 per thread.
// fp32 norms + positive dot; fp8 stores for both arrays.
__global__ void prep_kernel(const float* __restrict__ is_,
                            const float* __restrict__ js_) {
    __shared__ float s_p[8][3];
    int tid = threadIdx.x, lane = tid & 31, w = tid >> 5;
    int r   = blockIdx.x * 2 + (w >> 2);        // row 0..2047
    int e   = (tid & 127) * 2;                  // elem in row
    int off = r * D + e;

    float2 a = *(const float2*)(is_ + off);
    float2 b = *(const float2*)(js_ + off);

    float sa = a.x * a.x + a.y * a.y;
    float sb = b.x * b.x + b.y * b.y;
    float pd = a.x * b.x + a.y * b.y;
#pragma unroll
    for (int o = 16; o; o >>= 1) {
        sa += __shfl_xor_sync(0xffffffffu, sa, o);
        sb += __shfl_xor_sync(0xffffffffu, sb, o);
        pd += __shfl_xor_sync(0xffffffffu, pd, o);
    }
    if (lane == 0) { s_p[w][0] = sa; s_p[w][1] = sb; s_p[w][2] = pd; }

    unsigned short fa = __nv_cvt_float2_to_fp8x2(a, __NV_SATFINITE, __NV_E4M3);
    unsigned short fb = __nv_cvt_float2_to_fp8x2(b, __NV_SATFINITE, __NV_E4M3);
    *(unsigned short*)(g_is_f8 + off) = fa;
    *(unsigned short*)(g_js_f8 + off) = fb;

    __syncthreads();
    if (tid < 2) {
        int rr = blockIdx.x * 2 + tid;
        float qa = 0.f, qb = 0.f, qp = 0.f;
#pragma unroll
        for (int q = 0; q < 4; q++) {
            qa += s_p[4 * tid + q][0];
            qb += s_p[4 * tid + q][1];
            qp += s_p[4 * tid + q][2];
        }
        g_rn2_is[rr] = qa;
        g_rn2_js[rr] = qb;
        g_pd[rr]     = qp;
    }
}

// ---------------- kernel 2: tiled gathered similarities ----------------
// grid = dim3(8, 16): blockIdx.x -> jb tile of 8, blockIdx.y -> anchor tile of 4.
// Stages anchor fp8 (32 KB) + jb blocks of js/is fp8 (64+64 KB) in smem;
// all gathers become LDS. Warp w: anchor (w&3), jb pair {w>>2, (w>>2)+4},
// computing sim_j AND sim_k for both jb's fused (anchor row read once).
__global__ void __launch_bounds__(512, 1)
sims_kernel(const int* __restrict__ idxj, const int* __restrict__ idxk) {
    extern __shared__ char smem[];
    int tid = threadIdx.x, lane = tid & 31, w = tid >> 5;
    int i0  = blockIdx.y * I_TILE;
    int jb0 = blockIdx.x * J_TILE;

    // ---- stage: contiguous copies ----
    {
        const uint4* sA = (const uint4*)(g_is_f8 + (size_t)i0 * F);
        const uint4* sJ = (const uint4*)(g_js_f8 + (size_t)jb0 * F);
        const uint4* sK = (const uint4*)(g_is_f8 + (size_t)jb0 * F);
        uint4* dA = (uint4*)(smem + SM_ANCH);
        uint4* dJ = (uint4*)(smem + SM_J8);
        uint4* dK = (uint4*)(smem + SM_K8);
#pragma unroll
        for (int t = 0; t < 4; t++) dA[tid + 512 * t] = sA[tid + 512 * t];   // 32 KB
#pragma unroll
        for (int t = 0; t < 8; t++) dJ[tid + 512 * t] = sJ[tid + 512 * t];   // 64 KB
#pragma unroll
        for (int t = 0; t < 8; t++) dK[tid + 512 * t] = sK[tid + 512 * t];   // 64 KB
    }
    if (tid < 256)
        ((float*)(smem + SM_RNJ))[tid] = g_rn2_js[jb0 * C + tid];
    else
        ((float*)(smem + SM_RNK))[tid - 256] = g_rn2_is[jb0 * C + (tid - 256)];
    if (w < I_TILE) {
        float v = g_rn2_is[(i0 + w) * C + lane];
#pragma unroll
        for (int o = 16; o; o >>= 1) v += __shfl_xor_sync(0xffffffffu, v, o);
        if (lane == 0) ((float*)(smem + SM_NA))[w] = sqrtf(v);
    }
    __syncthreads();

    int i_loc = w & 3;
    int jA = w >> 2, jB = jA + 4;            // local jb indices
    int i   = i0 + i_loc;
    int jb1 = jb0 + jA, jb2 = jb0 + jB;

    // indices (coalesced) + lane-parallel norm gathers from smem
    int mjA = idxj[((size_t)i * B + jb1) * C + lane];
    int mkA = idxk[((size_t)i * B + jb1) * C + lane];
    int mjB = idxj[((size_t)i * B + jb2) * C + lane];
    int mkB = idxk[((size_t)i * B + jb2) * C + lane];
    const float* rnj = (const float*)(smem + SM_RNJ);
    const float* rnk = (const float*)(smem + SM_RNK);
    float n2jA = rnj[jA * C + mjA], n2kA = rnk[jA * C + mkA];
    float n2jB = rnj[jB * C + mjB], n2kB = rnk[jB * C + mkB];
#pragma unroll
    for (int o = 16; o; o >>= 1) {
        n2jA += __shfl_xor_sync(0xffffffffu, n2jA, o);
        n2kA += __shfl_xor_sync(0xffffffffu, n2kA, o);
        n2jB += __shfl_xor_sync(0xffffffffu, n2jB, o);
        n2kB += __shfl_xor_sync(0xffffffffu, n2kB, o);
    }

    const char* anch  = smem + SM_ANCH + i_loc * 8192 + 8 * lane;
    const char* baseJ1 = smem + SM_J8 + jA * 8192 + 8 * lane;
    const char* baseK1 = smem + SM_K8 + jA * 8192 + 8 * lane;
    const char* baseJ2 = smem + SM_J8 + jB * 8192 + 8 * lane;
    const char* baseK2 = smem + SM_K8 + jB * 8192 + 8 * lane;

    float fjA = 0.f, fkA = 0.f, fjB = 0.f, fkB = 0.f;
#pragma unroll
    for (int cb = 0; cb < 4; cb++) {
        __half2 z = __float2half2_rn(0.f);
        __half2 hjA0 = z, hjA1 = z, hjA2 = z, hjA3 = z;
        __half2 hkA0 = z, hkA1 = z, hkA2 = z, hkA3 = z;
        __half2 hjB0 = z, hjB1 = z, hjB2 = z, hjB3 = z;
        __half2 hkB0 = z, hkB1 = z, hkB2 = z, hkB3 = z;
#pragma unroll
        for (int cc = 0; cc < 8; cc++) {
            int c = cb * 8 + cc;
            int rjA = __shfl_sync(0xffffffffu, mjA, c);
            int rkA = __shfl_sync(0xffffffffu, mkA, c);
            int rjB = __shfl_sync(0xffffffffu, mjB, c);
            int rkB = __shfl_sync(0xffffffffu, mkB, c);
            uint2 av = *(const uint2*)(anch + c * 256);            // 8 fp8 anchor
            __half2 a0 = f8_to_h2((unsigned short)(av.x & 0xffffu));
            __half2 a1 = f8_to_h2((unsigned short)(av.x >> 16));
            __half2 a2 = f8_to_h2((unsigned short)(av.y & 0xffffu));
            __half2 a3 = f8_to_h2((unsigned short)(av.y >> 16));
            uint2 vjA = *(const uint2*)(baseJ1 + rjA * 256);
            uint2 vkA = *(const uint2*)(baseK1 + rkA * 256);
            uint2 vjB = *(const uint2*)(baseJ2 + rjB * 256);
            uint2 vkB = *(const uint2*)(baseK2 + rkB * 256);
            hjA0 = __hfma2(a0, f8_to_h2((unsigned short)(vjA.x & 0xffffu)), hjA0);
            hjA1 = __hfma2(a1, f8_to_h2((unsigned short)(vjA.x >> 16)),     hjA1);
            hjA2 = __hfma2(a2, f8_to_h2((unsigned short)(vjA.y & 0xffffu)), hjA2);
            hjA3 = __hfma2(a3, f8_to_h2((unsigned short)(vjA.y >> 16)),     hjA3);
            hkA0 = __hfma2(a0, f8_to_h2((unsigned short)(vkA.x & 0xffffu)), hkA0);
            hkA1 = __hfma2(a1, f8_to_h2((unsigned short)(vkA.x >> 16)),     hkA1);
            hkA2 = __hfma2(a2, f8_to_h2((unsigned short)(vkA.y & 0xffffu)), hkA2);
            hkA3 = __hfma2(a3, f8_to_h2((unsigned short)(vkA.y >> 16)),     hkA3);
            hjB0 = __hfma2(a0, f8_to_h2((unsigned short)(vjB.x & 0xffffu)), hjB0);
            hjB1 = __hfma2(a1, f8_to_h2((unsigned short)(vjB.x >> 16)),     hjB1);
            hjB2 = __hfma2(a2, f8_to_h2((unsigned short)(vjB.y & 0xffffu)), hjB2);
            hjB3 = __hfma2(a3, f8_to_h2((unsigned short)(vjB.y >> 16)),     hjB3);
            hkB0 = __hfma2(a0, f8_to_h2((unsigned short)(vkB.x & 0xffffu)), hkB0);
            hkB1 = __hfma2(a1, f8_to_h2((unsigned short)(vkB.x >> 16)),     hkB1);
            hkB2 = __hfma2(a2, f8_to_h2((unsigned short)(vkB.y & 0xffffu)), hkB2);
            hkB3 = __hfma2(a3, f8_to_h2((unsigned short)(vkB.y >> 16)),     hkB3);
        }
        float2 t;
        t = __half22float2(__hadd2(__hadd2(hjA0, hjA1), __hadd2(hjA2, hjA3)));
        fjA += t.x + t.y;
        t = __half22float2(__hadd2(__hadd2(hkA0, hkA1), __hadd2(hkA2, hkA3)));
        fkA += t.x + t.y;
        t = __half22float2(__hadd2(__hadd2(hjB0, hjB1), __hadd2(hjB2, hjB3)));
        fjB += t.x + t.y;
        t = __half22float2(__hadd2(__hadd2(hkB0, hkB1), __hadd2(hkB2, hkB3)));
        fkB += t.x + t.y;
    }
#pragma unroll
    for (int o = 16; o; o >>= 1) {
        fjA += __shfl_xor_sync(0xffffffffu, fjA, o);
        fkA += __shfl_xor_sync(0xffffffffu, fkA, o);
        fjB += __shfl_xor_sync(0xffffffffu, fjB, o);
        fkB += __shfl_xor_sync(0xffffffffu, fkB, o);
    }
    if (lane == 0) {
        float na = ((const float*)(smem + SM_NA))[i_loc];
        g_sims[i][jb1]     = (jb1 == i) ? -INFINITY
                           : fjA / fmaxf(na * sqrtf(n2jA), EPS) / TEMP;
        g_sims[i][B + jb1] = (jb1 == i) ? -INFINITY
                           : fkA / fmaxf(na * sqrtf(n2kA), EPS) / TEMP;
        g_sims[i][jb2]     = (jb2 == i) ? -INFINITY
                           : fjB / fmaxf(na * sqrtf(n2jB), EPS) / TEMP;
        g_sims[i][B + jb2] = (jb2 == i) ? -INFINITY
                           : fkB / fmaxf(na * sqrtf(n2kB), EPS) / TEMP;
    }
}

// ---------------- kernel 3: logsumexp + fused final ----------------
__global__ void lse_kernel(float* __restrict__ out) {
    __shared__ float sred[4];
    __shared__ float s_bcast;
    __shared__ unsigned s_arrived;
    int i = blockIdx.x, tid = threadIdx.x, lane = tid & 31, w = tid >> 5;

    if (w == 0) {
        float pd  = g_pd[i * C + lane];
        float na2 = g_rn2_is[i * C + lane];
        float nb2 = g_rn2_js[i * C + lane];
#pragma unroll
        for (int o = 16; o; o >>= 1) {
            pd  += __shfl_xor_sync(0xffffffffu, pd, o);
            na2 += __shfl_xor_sync(0xffffffffu, na2, o);
            nb2 += __shfl_xor_sync(0xffffffffu, nb2, o);
        }
        if (lane == 0)
            s_bcast = pd / fmaxf(sqrtf(na2) * sqrtf(nb2), EPS) / TEMP;
    }
    __syncthreads();
    float pos = s_bcast;

    float my = g_sims[i][tid];
    float mx = fmaxf(my, pos);
#pragma unroll
    for (int o = 16; o; o >>= 1) mx = fmaxf(mx, __shfl_xor_sync(0xffffffffu, mx, o));
    if (lane == 0) sred[w] = mx;
    __syncthreads();
    mx = fmaxf(fmaxf(sred[0], sred[1]), fmaxf(sred[2], sred[3]));

    float e = expf(my - mx);                 // exp(-inf - mx) == 0 on diagonal
    if (tid == 0) e += expf(pos - mx);
#pragma unroll
    for (int o = 16; o; o >>= 1) e += __shfl_xor_sync(0xffffffffu, e, o);
    __syncthreads();
    if (lane == 0) sred[w] = e;
    __syncthreads();
    if (tid == 0) {
        float s = sred[0] + sred[1] + sred[2] + sred[3];
        g_lse[i] = logf(s) + mx - pos;
        __threadfence();
        s_arrived = atomicAdd(&g_done, 1u);   // old value
    }
    __syncthreads();

    if (s_arrived == B - 1) {                 // last block finishes the sum
        __threadfence();
        if (w == 0) {
            float v = g_lse[lane] + g_lse[lane + 32];
#pragma unroll
            for (int o = 16; o; o >>= 1) v += __shfl_xor_sync(0xffffffffu, v, o);
            if (lane == 0) {
                out[0] = v / (2.0f * B);
                atomicExch(&g_done, 0u);      // reset for next graph replay
            }
        }
    }
}

// ---------------- launch ----------------
extern "C" void kernel_launch(void* const* d_in, const int* in_sizes, int n_in,
                              void* d_out, int out_size) {
    const float* is_  = (const float*)d_in[0];   // children_is [B,C,D] f32
    const float* js_  = (const float*)d_in[1];   // children_js [B,C,D] f32
    const int*   idxj = (const int*)d_in[2];     // neg_idx_j  [B,B,C] i32
    const int*   idxk = (const int*)d_in[3];     // neg_idx_k  [B,B,C] i32
    float* out = (float*)d_out;

    static int smem_set = 0;
    if (!smem_set) {
        cudaFuncSetAttribute(sims_kernel,
                             cudaFuncAttributeMaxDynamicSharedMemorySize,
                             SM_TOTAL);
        smem_set = 1;
    }

    prep_kernel<<<BC / 2, 256>>>(is_, js_);                       // 1024 CTAs
    sims_kernel<<<dim3(B / J_TILE, B / I_TILE), 512, SM_TOTAL>>>(idxj, idxk);
    lse_kernel<<<B, 128>>>(out);
}

// round 11
// speedup vs baseline: 1.0167x; 1.0167x over previous
#include <cuda_runtime.h>
#include <math.h>

#define B 64
#define C 32
#define D 256
#define F (C * D)          // 8192
#define BC (B * C)         // 2048
#define TEMP 0.1f
#define EPS 1e-8f

#define QS      25.4f                   // 127/5: fixed int8 quant scale
#define QS2_INV (1.0f / (QS * QS))      // dequant factor for int dot

#define I_TILE 4
#define J_TILE 8
// dynamic smem layout (bytes)
#define SM_ANCH 0                       // 4 anchors int8: 4*8192 = 32768
#define SM_J8   32768                   // 8 jb blocks of js int8: 65536
#define SM_K8   98304                   // 8 jb blocks of is int8: 65536
#define SM_RNJ  163840                  // 256 floats
#define SM_RNK  164864                  // 256 floats
#define SM_NA   165888                  // 4 floats
#define SM_TOTAL 165920

// ---------------- scratch (no allocations allowed) ----------------
__device__ unsigned char g_is_q8[BC * D];   // int8 (512 KB)
__device__ unsigned char g_js_q8[BC * D];   // int8 (512 KB)
__device__ float g_rn2_is[BC];              // per-row squared norms (fp32, exact)
__device__ float g_rn2_js[BC];
__device__ float g_pd[BC];                  // per-row positive partial dots
__device__ float g_sims[B][2 * B];          // [i][0..B)=sim_j, [B..2B)=sim_k
__device__ float g_lse[B];                  // per-anchor (lse - pos)
__device__ unsigned g_done = 0;             // arrival counter for fused final

__device__ __forceinline__ int q8(float v) {
    int q = __float2int_rn(v * QS);
    return max(-127, min(127, q));
}

// ---------------- kernel 1: prep ----------------
// 1024 CTAs x 256 thr: 2 rows per CTA, 4 warps per row, float2 per thread.
// fp32 norms + positive dot (exact); int8 quantized stores for both arrays.
__global__ void prep_kernel(const float* __restrict__ is_,
                            const float* __restrict__ js_) {
    __shared__ float s_p[8][3];
    int tid = threadIdx.x, lane = tid & 31, w = tid >> 5;
    int r   = blockIdx.x * 2 + (w >> 2);        // row 0..2047
    int e   = (tid & 127) * 2;                  // elem in row
    int off = r * D + e;

    float2 a = *(const float2*)(is_ + off);
    float2 b = *(const float2*)(js_ + off);

    float sa = a.x * a.x + a.y * a.y;
    float sb = b.x * b.x + b.y * b.y;
    float pd = a.x * b.x + a.y * b.y;
#pragma unroll
    for (int o = 16; o; o >>= 1) {
        sa += __shfl_xor_sync(0xffffffffu, sa, o);
        sb += __shfl_xor_sync(0xffffffffu, sb, o);
        pd += __shfl_xor_sync(0xffffffffu, pd, o);
    }
    if (lane == 0) { s_p[w][0] = sa; s_p[w][1] = sb; s_p[w][2] = pd; }

    // int8 quantized stores (2 bytes each)
    unsigned short qa = (unsigned short)((q8(a.x) & 0xff) | ((q8(a.y) & 0xff) << 8));
    unsigned short qb = (unsigned short)((q8(b.x) & 0xff) | ((q8(b.y) & 0xff) << 8));
    *(unsigned short*)(g_is_q8 + off) = qa;
    *(unsigned short*)(g_js_q8 + off) = qb;

    __syncthreads();
    if (tid < 2) {
        int rr = blockIdx.x * 2 + tid;
        float qa2 = 0.f, qb2 = 0.f, qp = 0.f;
#pragma unroll
        for (int q = 0; q < 4; q++) {
            qa2 += s_p[4 * tid + q][0];
            qb2 += s_p[4 * tid + q][1];
            qp  += s_p[4 * tid + q][2];
        }
        g_rn2_is[rr] = qa2;
        g_rn2_js[rr] = qb2;
        g_pd[rr]     = qp;
    }
}

// ---------------- kernel 2: tiled gathered similarities (int8 + dp4a) ----------------
// grid = dim3(8, 16): blockIdx.x -> jb tile of 8, blockIdx.y -> anchor tile of 4.
// Stages anchor int8 (32 KB) + jb blocks of js/is int8 (64+64 KB) in smem.
// Warp w: anchor (w&3), jb pair {w>>2, (w>>2)+4}; 4 exact int32 dot streams
// via chained dp4a; dequantized once at the end.
__global__ void __launch_bounds__(512, 1)
sims_kernel(const int* __restrict__ idxj, const int* __restrict__ idxk) {
    extern __shared__ char smem[];
    int tid = threadIdx.x, lane = tid & 31, w = tid >> 5;
    int i0  = blockIdx.y * I_TILE;
    int jb0 = blockIdx.x * J_TILE;

    // ---- stage: contiguous copies ----
    {
        const uint4* sA = (const uint4*)(g_is_q8 + (size_t)i0 * F);
        const uint4* sJ = (const uint4*)(g_js_q8 + (size_t)jb0 * F);
        const uint4* sK = (const uint4*)(g_is_q8 + (size_t)jb0 * F);
        uint4* dA = (uint4*)(smem + SM_ANCH);
        uint4* dJ = (uint4*)(smem + SM_J8);
        uint4* dK = (uint4*)(smem + SM_K8);
#pragma unroll
        for (int t = 0; t < 4; t++) dA[tid + 512 * t] = sA[tid + 512 * t];   // 32 KB
#pragma unroll
        for (int t = 0; t < 8; t++) dJ[tid + 512 * t] = sJ[tid + 512 * t];   // 64 KB
#pragma unroll
        for (int t = 0; t < 8; t++) dK[tid + 512 * t] = sK[tid + 512 * t];   // 64 KB
    }
    if (tid < 256)
        ((float*)(smem + SM_RNJ))[tid] = g_rn2_js[jb0 * C + tid];
    else
        ((float*)(smem + SM_RNK))[tid - 256] = g_rn2_is[jb0 * C + (tid - 256)];
    if (w < I_TILE) {
        float v = g_rn2_is[(i0 + w) * C + lane];
#pragma unroll
        for (int o = 16; o; o >>= 1) v += __shfl_xor_sync(0xffffffffu, v, o);
        if (lane == 0) ((float*)(smem + SM_NA))[w] = sqrtf(v);
    }
    __syncthreads();

    int i_loc = w & 3;
    int jA = w >> 2, jB = jA + 4;            // local jb indices
    int i   = i0 + i_loc;
    int jb1 = jb0 + jA, jb2 = jb0 + jB;

    // indices (coalesced) + lane-parallel norm gathers from smem
    int mjA = idxj[((size_t)i * B + jb1) * C + lane];
    int mkA = idxk[((size_t)i * B + jb1) * C + lane];
    int mjB = idxj[((size_t)i * B + jb2) * C + lane];
    int mkB = idxk[((size_t)i * B + jb2) * C + lane];
    const float* rnj = (const float*)(smem + SM_RNJ);
    const float* rnk = (const float*)(smem + SM_RNK);
    float n2jA = rnj[jA * C + mjA], n2kA = rnk[jA * C + mkA];
    float n2jB = rnj[jB * C + mjB], n2kB = rnk[jB * C + mkB];
#pragma unroll
    for (int o = 16; o; o >>= 1) {
        n2jA += __shfl_xor_sync(0xffffffffu, n2jA, o);
        n2kA += __shfl_xor_sync(0xffffffffu, n2kA, o);
        n2jB += __shfl_xor_sync(0xffffffffu, n2jB, o);
        n2kB += __shfl_xor_sync(0xffffffffu, n2kB, o);
    }

    const char* anch   = smem + SM_ANCH + i_loc * 8192 + 8 * lane;
    const char* baseJ1 = smem + SM_J8 + jA * 8192 + 8 * lane;
    const char* baseK1 = smem + SM_K8 + jA * 8192 + 8 * lane;
    const char* baseJ2 = smem + SM_J8 + jB * 8192 + 8 * lane;
    const char* baseK2 = smem + SM_K8 + jB * 8192 + 8 * lane;

    int ijA = 0, ikA = 0, ijB = 0, ikB = 0;   // exact int32 dot accumulators
#pragma unroll
    for (int c = 0; c < C; c++) {
        int rjA = __shfl_sync(0xffffffffu, mjA, c);
        int rkA = __shfl_sync(0xffffffffu, mkA, c);
        int rjB = __shfl_sync(0xffffffffu, mjB, c);
        int rkB = __shfl_sync(0xffffffffu, mkB, c);
        uint2 av  = *(const uint2*)(anch + c * 256);       // 8 int8 anchor
        uint2 vjA = *(const uint2*)(baseJ1 + rjA * 256);
        uint2 vkA = *(const uint2*)(baseK1 + rkA * 256);
        uint2 vjB = *(const uint2*)(baseJ2 + rjB * 256);
        uint2 vkB = *(const uint2*)(baseK2 + rkB * 256);
        ijA = __dp4a((int)av.x, (int)vjA.x, __dp4a((int)av.y, (int)vjA.y, ijA));
        ikA = __dp4a((int)av.x, (int)vkA.x, __dp4a((int)av.y, (int)vkA.y, ikA));
        ijB = __dp4a((int)av.x, (int)vjB.x, __dp4a((int)av.y, (int)vjB.y, ijB));
        ikB = __dp4a((int)av.x, (int)vkB.x, __dp4a((int)av.y, (int)vkB.y, ikB));
    }
    // exact integer cross-lane reduction
#pragma unroll
    for (int o = 16; o; o >>= 1) {
        ijA += __shfl_xor_sync(0xffffffffu, ijA, o);
        ikA += __shfl_xor_sync(0xffffffffu, ikA, o);
        ijB += __shfl_xor_sync(0xffffffffu, ijB, o);
        ikB += __shfl_xor_sync(0xffffffffu, ikB, o);
    }
    if (lane == 0) {
        float na = ((const float*)(smem + SM_NA))[i_loc];
        float fjA = (float)ijA * QS2_INV;
        float fkA = (float)ikA * QS2_INV;
        float fjB = (float)ijB * QS2_INV;
        float fkB = (float)ikB * QS2_INV;
        g_sims[i][jb1]     = (jb1 == i) ? -INFINITY
                           : fjA / fmaxf(na * sqrtf(n2jA), EPS) / TEMP;
        g_sims[i][B + jb1] = (jb1 == i) ? -INFINITY
                           : fkA / fmaxf(na * sqrtf(n2kA), EPS) / TEMP;
        g_sims[i][jb2]     = (jb2 == i) ? -INFINITY
                           : fjB / fmaxf(na * sqrtf(n2jB), EPS) / TEMP;
        g_sims[i][B + jb2] = (jb2 == i) ? -INFINITY
                           : fkB / fmaxf(na * sqrtf(n2kB), EPS) / TEMP;
    }
}

// ---------------- kernel 3: logsumexp + fused final ----------------
__global__ void lse_kernel(float* __restrict__ out) {
    __shared__ float sred[4];
    __shared__ float s_bcast;
    __shared__ unsigned s_arrived;
    int i = blockIdx.x, tid = threadIdx.x, lane = tid & 31, w = tid >> 5;

    if (w == 0) {
        float pd  = g_pd[i * C + lane];
        float na2 = g_rn2_is[i * C + lane];
        float nb2 = g_rn2_js[i * C + lane];
#pragma unroll
        for (int o = 16; o; o >>= 1) {
            pd  += __shfl_xor_sync(0xffffffffu, pd, o);
            na2 += __shfl_xor_sync(0xffffffffu, na2, o);
            nb2 += __shfl_xor_sync(0xffffffffu, nb2, o);
        }
        if (lane == 0)
            s_bcast = pd / fmaxf(sqrtf(na2) * sqrtf(nb2), EPS) / TEMP;
    }
    __syncthreads();
    float pos = s_bcast;

    float my = g_sims[i][tid];
    float mx = fmaxf(my, pos);
#pragma unroll
    for (int o = 16; o; o >>= 1) mx = fmaxf(mx, __shfl_xor_sync(0xffffffffu, mx, o));
    if (lane == 0) sred[w] = mx;
    __syncthreads();
    mx = fmaxf(fmaxf(sred[0], sred[1]), fmaxf(sred[2], sred[3]));

    float e = expf(my - mx);                 // exp(-inf - mx) == 0 on diagonal
    if (tid == 0) e += expf(pos - mx);
#pragma unroll
    for (int o = 16; o; o >>= 1) e += __shfl_xor_sync(0xffffffffu, e, o);
    __syncthreads();
    if (lane == 0) sred[w] = e;
    __syncthreads();
    if (tid == 0) {
        float s = sred[0] + sred[1] + sred[2] + sred[3];
        g_lse[i] = logf(s) + mx - pos;
        __threadfence();
        s_arrived = atomicAdd(&g_done, 1u);   // old value
    }
    __syncthreads();

    if (s_arrived == B - 1) {                 // last block finishes the sum
        __threadfence();
        if (w == 0) {
            float v = g_lse[lane] + g_lse[lane + 32];
#pragma unroll
            for (int o = 16; o; o >>= 1) v += __shfl_xor_sync(0xffffffffu, v, o);
            if (lane == 0) {
                out[0] = v / (2.0f * B);
                atomicExch(&g_done, 0u);      // reset for next graph replay
            }
        }
    }
}

// ---------------- launch ----------------
extern "C" void kernel_launch(void* const* d_in, const int* in_sizes, int n_in,
                              void* d_out, int out_size) {
    const float* is_  = (const float*)d_in[0];   // children_is [B,C,D] f32
    const float* js_  = (const float*)d_in[1];   // children_js [B,C,D] f32
    const int*   idxj = (const int*)d_in[2];     // neg_idx_j  [B,B,C] i32
    const int*   idxk = (const int*)d_in[3];     // neg_idx_k  [B,B,C] i32
    float* out = (float*)d_out;

    static int smem_set = 0;
    if (!smem_set) {
        cudaFuncSetAttribute(sims_kernel,
                             cudaFuncAttributeMaxDynamicSharedMemorySize,
                             SM_TOTAL);
        smem_set = 1;
    }

    prep_kernel<<<BC / 2, 256>>>(is_, js_);                       // 1024 CTAs
    sims_kernel<<<dim3(B / J_TILE, B / I_TILE), 512, SM_TOTAL>>>(idxj, idxk);
    lse_kernel<<<B, 128>>>(out);
}